// round 2
// baseline (speedup 1.0000x reference)
#include <cuda_runtime.h>
#include <cuda_bf16.h>

// ROI bilinear pooling (tf.image.resize half-pixel-center semantics, per ROI).
// img:  (1, 64, 64, 1024) float32, NHWC
// rois: (1, R, 4) int32  [x, y, w, h]
// out:  (1, R, 7, 7, 1024) float32
//
// One CTA per output pixel (r, py, px); 256 threads x float4 = 1024 channels.
// Coordinate math is scalar, amortized over the 1024-channel vector blend.

#define POOL 7
#define HW   64
#define C    1024

__global__ __launch_bounds__(256) void roi_pool_kernel(
    const float* __restrict__ img,
    const int*   __restrict__ rois,
    float*       __restrict__ out)
{
    const int idx = blockIdx.x;          // r*49 + py*7 + px
    const int r  = idx / (POOL * POOL);
    const int p  = idx - r * (POOL * POOL);
    const int py = p / POOL;
    const int px = p - py * POOL;

    // ROI box (broadcast load; all threads same address -> L1/L2 broadcast)
    const int4 roi = __ldg(((const int4*)rois) + r);
    const int bx = roi.x, by = roi.y, bw = roi.z, bh = roi.w;

    // Vertical source coords (half-pixel centers, unclipped lerp like reference)
    const float sy = (py + 0.5f) * ((float)bh / (float)POOL) - 0.5f;
    const float fy = floorf(sy);
    const float ty = sy - fy;
    const int   iy = (int)fy;
    const int   y0 = by + min(max(iy,     0), bh - 1);
    const int   y1 = by + min(max(iy + 1, 0), bh - 1);

    // Horizontal source coords
    const float sx = (px + 0.5f) * ((float)bw / (float)POOL) - 0.5f;
    const float fx = floorf(sx);
    const float tx = sx - fx;
    const int   ix = (int)fx;
    const int   x0 = bx + min(max(ix,     0), bw - 1);
    const int   x1 = bx + min(max(ix + 1, 0), bw - 1);

    const float4* p00 = (const float4*)(img + ((size_t)(y0 * HW + x0)) * C);
    const float4* p01 = (const float4*)(img + ((size_t)(y0 * HW + x1)) * C);
    const float4* p10 = (const float4*)(img + ((size_t)(y1 * HW + x0)) * C);
    const float4* p11 = (const float4*)(img + ((size_t)(y1 * HW + x1)) * C);

    const int c = threadIdx.x;           // 0..255, each handles one float4

    const float4 a = __ldg(p00 + c);
    const float4 b = __ldg(p01 + c);
    const float4 g = __ldg(p10 + c);
    const float4 d = __ldg(p11 + c);

    const float wtx0 = 1.0f - tx;
    const float wty0 = 1.0f - ty;

    float4 o;
    {
        float top = a.x * wtx0 + b.x * tx;
        float bot = g.x * wtx0 + d.x * tx;
        o.x = top * wty0 + bot * ty;
    }
    {
        float top = a.y * wtx0 + b.y * tx;
        float bot = g.y * wtx0 + d.y * tx;
        o.y = top * wty0 + bot * ty;
    }
    {
        float top = a.z * wtx0 + b.z * tx;
        float bot = g.z * wtx0 + d.z * tx;
        o.z = top * wty0 + bot * ty;
    }
    {
        float top = a.w * wtx0 + b.w * tx;
        float bot = g.w * wtx0 + d.w * tx;
        o.w = top * wty0 + bot * ty;
    }

    ((float4*)out)[(size_t)idx * (C / 4) + c] = o;
}

extern "C" void kernel_launch(void* const* d_in, const int* in_sizes, int n_in,
                              void* d_out, int out_size)
{
    const float* img  = (const float*)d_in[0];
    const int*   rois = (const int*)d_in[1];
    float*       out  = (float*)d_out;

    const int R = in_sizes[1] / 4;       // rois element count / 4 = number of ROIs
    const int blocks = R * POOL * POOL;  // one CTA per output pixel

    roi_pool_kernel<<<blocks, 256>>>(img, rois, out);
}